// round 1
// baseline (speedup 1.0000x reference)
#include <cuda_runtime.h>
#include <math.h>
#include <float.h>

// Problem constants
#define NB      8192   // batch
#define ENCD    256    // encoding dim
#define NCL     32     // clusters
#define KSEL    25     // k (threshold = sorted[25])
#define KEEP    26     // track 26 smallest
#define BM      32     // rows per CTA
#define BN      64     // cols per j-tile
#define KC      64     // k-chunk
#define NTHR    256

// Scratch (no cudaMalloc allowed)
__device__ float g_sq[NB];
__device__ float g_maxp[NB];
__device__ int   g_cid[NB];

// ---------------------------------------------------------------------------
// Prep: per-row sum-of-squares of encodings; argmax/max of categorical.
// One warp per row.
// ---------------------------------------------------------------------------
__global__ void prep_kernel(const float* __restrict__ enc,
                            const float* __restrict__ cat) {
    int warp = (blockIdx.x * blockDim.x + threadIdx.x) >> 5;
    int lane = threadIdx.x & 31;
    if (warp >= NB) return;

    const float* e = enc + (size_t)warp * ENCD;
    float s = 0.f;
#pragma unroll
    for (int i = 0; i < ENCD / 32; ++i) {
        float v = e[lane + 32 * i];
        s += v * v;
    }
#pragma unroll
    for (int off = 16; off; off >>= 1)
        s += __shfl_xor_sync(0xffffffffu, s, off);

    float v = cat[(size_t)warp * NCL + lane];
    int idx = lane;
#pragma unroll
    for (int off = 16; off; off >>= 1) {
        float ov = __shfl_xor_sync(0xffffffffu, v, off);
        int   oi = __shfl_xor_sync(0xffffffffu, idx, off);
        if (ov > v || (ov == v && oi < idx)) { v = ov; idx = oi; }
    }
    if (lane == 0) {
        g_sq[warp]   = s;
        g_maxp[warp] = v;
        g_cid[warp]  = idx;
    }
}

// ---------------------------------------------------------------------------
// Fused kernel: per CTA, 32 rows. Stream all 8192 columns in 64-wide tiles.
// Tiled fp32 GEMM (A resident transposed in smem, B chunked + XOR-swizzled),
// fused epilogue maintains per-row sorted 26-smallest (d2, cluster_id).
// Final: entropy * max_prob.
// ---------------------------------------------------------------------------
// Dynamic smem layout (floats):
//   AsT   [ENCD][BM]      8192
//   Bsh   [KC][BN]        4096   (16B-group XOR swizzle)
//   c_val [BM][BN]        2048
//   c_cid [BM][BN]        2048 (int)
//   s_val [BM][KEEP]       832
//   s_cid [BM][KEEP]       832 (int)
//   s_sqA [BM]              32
//   s_sqB [BN]              64
//   s_cidB[BN]              64 (int)
//   s_thr [BM]              32
//   s_cnt [BM]              32 (int)
//   c_n   [BM]              32 (int)
#define SMEM_FLOATS (8192 + 4096 + 2048 + 2048 + 832 + 832 + 32 + 64 + 64 + 32 + 32 + 32)
#define SMEM_BYTES  (SMEM_FLOATS * 4)

__global__ void __launch_bounds__(NTHR)
cluster_main(const float* __restrict__ E, float* __restrict__ out) {
    extern __shared__ float smem[];
    float* AsT    = smem;                       // 8192
    float* Bsh    = AsT + 8192;                 // 4096
    float* c_val  = Bsh + 4096;                 // 2048
    int*   c_cid  = (int*)(c_val + 2048);       // 2048
    float* s_val  = (float*)(c_cid + 2048);     // 832
    int*   s_cid  = (int*)(s_val + 832);        // 832
    float* s_sqA  = (float*)(s_cid + 832);      // 32
    float* s_sqB  = s_sqA + 32;                 // 64
    int*   s_cidB = (int*)(s_sqB + 64);         // 64
    float* s_thr  = (float*)(s_cidB + 64);      // 32
    int*   s_cnt  = (int*)(s_thr + 32);         // 32
    int*   c_n    = s_cnt + 32;                 // 32

    const int tid  = threadIdx.x;
    const int tx   = tid & 15;     // col quad in compute
    const int ty   = tid >> 4;     // row pair in compute
    const int row0 = blockIdx.x * BM;

    // Load A rows [row0, row0+32) transposed into AsT[k][r].
    for (int f = tid; f < BM * (ENCD / 4); f += NTHR) {
        int r  = f >> 6;       // 64 float4 per row
        int kq = f & 63;
        float4 v = *(const float4*)(E + (size_t)(row0 + r) * ENCD + kq * 4);
        AsT[(kq * 4 + 0) * BM + r] = v.x;
        AsT[(kq * 4 + 1) * BM + r] = v.y;
        AsT[(kq * 4 + 2) * BM + r] = v.z;
        AsT[(kq * 4 + 3) * BM + r] = v.w;
    }
    if (tid < BM) {
        s_sqA[tid] = g_sq[row0 + tid];
        s_thr[tid] = FLT_MAX;
        s_cnt[tid] = 0;
        c_n[tid]   = 0;
    }
    __syncthreads();

    // Loader mapping for B tiles: m = k-quad, jgq = j-quad, g = swizzled group.
    const int m   = tid & 15;
    const int jgq = tid >> 4;
    const int g   = jgq ^ m;

    for (int jb = 0; jb < NB / BN; ++jb) {
        if (tid < BN) {
            int j = jb * BN + tid;
            s_sqB[tid]  = g_sq[j];
            s_cidB[tid] = g_cid[j];
        }

        float acc[2][4] = {{0.f, 0.f, 0.f, 0.f}, {0.f, 0.f, 0.f, 0.f}};

#pragma unroll 1
        for (int kc = 0; kc < ENCD / KC; ++kc) {
            // Stage B chunk: each thread reads a 4x4 block (4 float4 from 4
            // consecutive j rows), transposes in registers, stores k-major
            // with 16B XOR swizzle (group = jgq ^ m) -> conflict-free.
            const float* src = E + (size_t)(jb * BN + jgq * 4) * ENCD + kc * KC + m * 4;
            float4 r0v = *(const float4*)(src);
            float4 r1v = *(const float4*)(src + ENCD);
            float4 r2v = *(const float4*)(src + 2 * ENCD);
            float4 r3v = *(const float4*)(src + 3 * ENCD);

            __syncthreads();  // previous chunk's compute done
            {
                float* dst = Bsh + (m * 4) * BN + g * 4;
                ((float4*)dst)[0]          = make_float4(r0v.x, r1v.x, r2v.x, r3v.x);
                *(float4*)(dst + BN)       = make_float4(r0v.y, r1v.y, r2v.y, r3v.y);
                *(float4*)(dst + 2 * BN)   = make_float4(r0v.z, r1v.z, r2v.z, r3v.z);
                *(float4*)(dst + 3 * BN)   = make_float4(r0v.w, r1v.w, r2v.w, r3v.w);
            }
            __syncthreads();

            const float* aBase = AsT + (kc * KC) * BM + (ty << 1);
#pragma unroll 16
            for (int kk = 0; kk < KC; ++kk) {
                float2 a = *(const float2*)(aBase + kk * BM);
                const float4 b =
                    *(const float4*)&Bsh[kk * BN + ((tx ^ ((kk >> 2) & 15)) << 2)];
                acc[0][0] += a.x * b.x; acc[0][1] += a.x * b.y;
                acc[0][2] += a.x * b.z; acc[0][3] += a.x * b.w;
                acc[1][0] += a.y * b.x; acc[1][1] += a.y * b.y;
                acc[1][2] += a.y * b.z; acc[1][3] += a.y * b.w;
            }
        }

        // Epilogue: form clamped d2, collect candidates below current thr.
        {
            const int r0 = ty * 2, r1 = r0 + 1;
            const float sq0 = s_sqA[r0], sq1 = s_sqA[r1];
            const float thr0 = s_thr[r0], thr1 = s_thr[r1];
#pragma unroll
            for (int q = 0; q < 4; ++q) {
                int   jl = (tx << 2) + q;
                float sb = s_sqB[jl];
                int   cj = s_cidB[jl];
                float d0 = fmaxf(sq0 + sb - 2.f * acc[0][q], 0.f);
                float d1 = fmaxf(sq1 + sb - 2.f * acc[1][q], 0.f);
                if (d0 < thr0) {
                    int p = atomicAdd(&c_n[r0], 1);
                    c_val[r0 * BN + p] = d0; c_cid[r0 * BN + p] = cj;
                }
                if (d1 < thr1) {
                    int p = atomicAdd(&c_n[r1], 1);
                    c_val[r1 * BN + p] = d1; c_cid[r1 * BN + p] = cj;
                }
            }
        }
        __syncthreads();

        // One maintainer thread per row: merge candidates into sorted top-26.
        if (tid < BM) {
            const int row = tid;
            int    n   = c_n[row];
            int    cnt = s_cnt[row];
            float* rv  = s_val + row * KEEP;
            int*   rc  = s_cid + row * KEEP;
            for (int i = 0; i < n; ++i) {
                float v = c_val[row * BN + i];
                int   c = c_cid[row * BN + i];
                if (cnt < KEEP) {
                    int p = cnt++;
                    while (p > 0 && rv[p - 1] > v) {
                        rv[p] = rv[p - 1]; rc[p] = rc[p - 1]; --p;
                    }
                    rv[p] = v; rc[p] = c;
                } else if (v < rv[KEEP - 1]) {
                    int p = KEEP - 1;
                    while (p > 0 && rv[p - 1] > v) {
                        rv[p] = rv[p - 1]; rc[p] = rc[p - 1]; --p;
                    }
                    rv[p] = v; rc[p] = c;
                }
            }
            s_cnt[row] = cnt;
            s_thr[row] = (cnt == KEEP) ? rv[KEEP - 1] : FLT_MAX;
            c_n[row]   = 0;
        }
        __syncthreads();
    }

    // Final: neighbors = entries strictly below rv[25]; entropy over cluster
    // counts; scale by max prob. Matches reference expression incl. +1e-5.
    if (tid < BM) {
        const int row = tid;
        float* rv = s_val + row * KEEP;
        int*   rc = s_cid + row * KEEP;
        float  thr = rv[KEEP - 1];
        int n = 0;
        while (n < KSEL && rv[n] < thr) ++n;
        float fn  = (float)n;
        float ent = 0.f;
        for (int p = 0; p < n; ++p) {
            bool first = true;
            for (int q = 0; q < p; ++q)
                if (rc[q] == rc[p]) { first = false; break; }
            if (!first) continue;
            int cc = 1;
            for (int q = p + 1; q < n; ++q) cc += (rc[q] == rc[p]);
            float bins = (float)cc / fn;
            ent -= bins * logf(bins + 1e-5f);
        }
        out[row0 + row] = ent * g_maxp[row0 + row];
    }
}

// ---------------------------------------------------------------------------
extern "C" void kernel_launch(void* const* d_in, const int* in_sizes, int n_in,
                              void* d_out, int out_size) {
    const float* enc = (const float*)d_in[0];
    const float* cat = (const float*)d_in[1];
    float* out = (float*)d_out;

    cudaFuncSetAttribute(cluster_main,
                         cudaFuncAttributeMaxDynamicSharedMemorySize,
                         SMEM_BYTES);

    prep_kernel<<<NB * 32 / NTHR, NTHR>>>(enc, cat);
    cluster_main<<<NB / BM, NTHR, SMEM_BYTES>>>(enc, out);
}

// round 3
// speedup vs baseline: 1.2925x; 1.2925x over previous
#include <cuda_runtime.h>
#include <cuda_bf16.h>
#include <math.h>
#include <float.h>
#include <stdint.h>

#define NB    8192
#define ENCD  256
#define NCL   32
#define KSEL  25
#define KEEP  26
#define BM    64          // rows per CTA
#define BN    32          // cols per tile
#define NT    (NB / BN)   // 256 tiles
#define NTHR  256

// ---------------- device scratch ----------------
__device__ float    g_sq[NB];
__device__ float    g_maxp[NB];
__device__ int      g_cid[NB];
// Pre-swizzled bf16 blobs: per 32-row block jb, 32KB = [hi 16KB | lo 16KB],
// row stride 512B, per-row 16B-chunk XOR swizzle (c ^ (r&7)).
__device__ uint32_t g_Bblk[NB * 256];   // 8 MB

// ---------------- helpers ----------------
__device__ __forceinline__ uint32_t smem_to_u32(const void* p) {
    uint32_t a;
    asm("{ .reg .u64 t; cvta.to.shared.u64 t, %1; cvt.u32.u64 %0, t; }" : "=r"(a) : "l"(p));
    return a;
}
__device__ __forceinline__ void cp16(uint32_t s, const void* g) {
    asm volatile("cp.async.cg.shared.global [%0], [%1], 16;" :: "r"(s), "l"(g) : "memory");
}
__device__ __forceinline__ void cp_commit() {
    asm volatile("cp.async.commit_group;" ::: "memory");
}
template <int N>
__device__ __forceinline__ void cp_wait() {
    asm volatile("cp.async.wait_group %0;" :: "n"(N) : "memory");
}
#define LDSM4(r0, r1, r2, r3, addr) \
    asm volatile("ldmatrix.sync.aligned.m8n8.x4.shared.b16 {%0,%1,%2,%3}, [%4];" \
                 : "=r"(r0), "=r"(r1), "=r"(r2), "=r"(r3) : "r"(addr))
#define MMA16816(d, a0, a1, a2, a3, b0, b1) \
    asm volatile("mma.sync.aligned.m16n8k16.row.col.f32.bf16.bf16.f32 " \
                 "{%0,%1,%2,%3}, {%4,%5,%6,%7}, {%8,%9}, {%0,%1,%2,%3};" \
                 : "+f"((d)[0]), "+f"((d)[1]), "+f"((d)[2]), "+f"((d)[3]) \
                 : "r"(a0), "r"(a1), "r"(a2), "r"(a3), "r"(b0), "r"(b1))

// ---------------- smem layout (bytes) ----------------
#define SM_A     0        // 64KB: A hi [64][512B] then A lo
#define SM_B     65536    // 2 x 32KB B tile bufs ([hi 16KB | lo 16KB] each)
#define SM_D     131072   // 2 x 8704B: D per k-half, [64][34] f32
#define SM_SLV   148480   // 128 x 26 f32 selection values
#define SM_SLC   161792   // 128 x 26 int cluster ids
#define SM_SQA   175104   // 64 f32
#define SM_SQB   175360   // 2 x 32 f32
#define SM_CIDB  175616   // 2 x 32 int
#define SMEM_BYTES 175872

// ---------------------------------------------------------------------------
// prep1: row sum-of-squares; argmax/max of categorical. One warp per row.
// ---------------------------------------------------------------------------
__global__ void prep_kernel(const float* __restrict__ enc,
                            const float* __restrict__ cat) {
    int warp = (blockIdx.x * blockDim.x + threadIdx.x) >> 5;
    int lane = threadIdx.x & 31;
    if (warp >= NB) return;

    const float* e = enc + (size_t)warp * ENCD;
    float s = 0.f;
#pragma unroll
    for (int i = 0; i < ENCD / 32; ++i) { float v = e[lane + 32 * i]; s += v * v; }
#pragma unroll
    for (int off = 16; off; off >>= 1) s += __shfl_xor_sync(0xffffffffu, s, off);

    float v = cat[(size_t)warp * NCL + lane];
    int idx = lane;
#pragma unroll
    for (int off = 16; off; off >>= 1) {
        float ov = __shfl_xor_sync(0xffffffffu, v, off);
        int   oi = __shfl_xor_sync(0xffffffffu, idx, off);
        if (ov > v || (ov == v && oi < idx)) { v = ov; idx = oi; }
    }
    if (lane == 0) { g_sq[warp] = s; g_maxp[warp] = v; g_cid[warp] = idx; }
}

// ---------------------------------------------------------------------------
// prep2: bf16 hi/lo split into pre-swizzled 32-row blobs.
// Thread per (block jb, row r, 16B-chunk c): reads 8 f32, writes hi/lo 16B.
// ---------------------------------------------------------------------------
__global__ void prep_b_kernel(const float* __restrict__ E) {
    int gid = blockIdx.x * blockDim.x + threadIdx.x;   // NB*32 threads
    int jb = gid >> 10;
    int r  = (gid >> 5) & 31;
    int c  = gid & 31;

    const float* src = E + (size_t)(jb * 32 + r) * ENCD + c * 8;
    float4 v0 = *(const float4*)src;
    float4 v1 = *(const float4*)(src + 4);
    float f[8] = {v0.x, v0.y, v0.z, v0.w, v1.x, v1.y, v1.z, v1.w};

    uint32_t hi[4], lo[4];
#pragma unroll
    for (int i = 0; i < 4; ++i) {
        __nv_bfloat16 h0 = __float2bfloat16(f[2 * i]);
        __nv_bfloat16 h1 = __float2bfloat16(f[2 * i + 1]);
        __nv_bfloat16 l0 = __float2bfloat16(f[2 * i] - __bfloat162float(h0));
        __nv_bfloat16 l1 = __float2bfloat16(f[2 * i + 1] - __bfloat162float(h1));
        __nv_bfloat162 hp; hp.x = h0; hp.y = h1;
        __nv_bfloat162 lp; lp.x = l0; lp.y = l1;
        hi[i] = *(uint32_t*)&hp;
        lo[i] = *(uint32_t*)&lp;
    }

    int base = jb * 8192;                                   // u32 units (32KB blob)
    int off  = (r * 512 + ((c ^ (r & 7)) << 4)) >> 2;       // u32 units
    *(uint4*)(g_Bblk + base + off)        = make_uint4(hi[0], hi[1], hi[2], hi[3]);
    *(uint4*)(g_Bblk + base + 4096 + off) = make_uint4(lo[0], lo[1], lo[2], lo[3]);
}

// ---------------------------------------------------------------------------
// Main: 128 CTAs x 64 rows; sweep 256 column tiles of 32.
// 8 warps: warpM = wid&3 (16 rows), kh = wid>>2 (k half of 128).
// Per tile: 3-term bf16 HMMA into 16 f32 accums -> D[kh] smem -> selection.
// ---------------------------------------------------------------------------
__global__ void __launch_bounds__(NTHR, 1)
hmma_main(float* __restrict__ out) {
    extern __shared__ char smem[];
    const uint32_t sb = smem_to_u32(smem);
    const int tid  = threadIdx.x;
    const int lane = tid & 31;
    const int wid  = tid >> 5;
    const int warpM = wid & 3;
    const int kh    = wid >> 2;
    const int row0  = blockIdx.x * BM;
    const int b2    = blockIdx.x * 2;   // blob pair for A

    // ---- prologue: async copies of A (64KB) and B tiles 0,1 (32KB each) ----
#pragma unroll
    for (int i = 0; i < 16; ++i) {
        int ck = tid + i * 256;                 // 0..4095 16B chunks
        int piece = ck >> 10;                   // 0: b0.hi 1: b1.hi 2: b0.lo 3: b1.lo
        const uint32_t* src = g_Bblk + (size_t)(b2 + (piece & 1)) * 8192
                                     + (size_t)(piece >> 1) * 4096 + (ck & 1023) * 4;
        cp16(sb + SM_A + ck * 16, src);
    }
    cp_commit();
#pragma unroll
    for (int buf = 0; buf < 2; ++buf) {
#pragma unroll
        for (int i = 0; i < 8; ++i) {
            int ck = tid + i * 256;             // 0..2047
            cp16(sb + SM_B + buf * 32768 + ck * 16, g_Bblk + (size_t)buf * 8192 + ck * 4);
        }
        cp_commit();
    }
    if (tid < BM) ((float*)(smem + SM_SQA))[tid] = g_sq[row0 + tid];
    cp_wait<1>();   // A + B0 done, B1 in flight
    __syncthreads();

    // ---- ldmatrix lane addressing ----
    const int lr = lane & 7, gq = lane >> 3;
    // A: sub order (r0-7,c0)(r8-15,c0)(r0-7,c1)(r8-15,c1)
    const int a_row = warpM * 16 + ((gq & 1) << 3) + lr;
    const uint32_t a_rbase = sb + SM_A + a_row * 512;
    const int a_sw  = a_row & 7;
    const int a_cad = gq >> 1;
    // B: sub order (n0-7,c0)(n0-7,c1)(n8-15,c0)(n8-15,c1); row%8 == lr
    const uint32_t boff1 = (((gq >> 1) << 3) + lr) * 512;
    const uint32_t boff2 = boff1 + 8192;        // +16 rows
    const int b_cad = gq & 1;

    // selection state
    float thr = FLT_MAX;
    int   cnt = 0;
    const int selrow = tid >> 1, selh = tid & 1;
    float sqa_r = (tid < 128) ? ((float*)(smem + SM_SQA))[selrow] : 0.f;
    float* rv = (float*)(smem + SM_SLV) + tid * KEEP;
    int*   rc = (int*)(smem + SM_SLC) + tid * KEEP;

    for (int t = 0; t < NT; ++t) {
        const int p = t & 1;
        const uint32_t Bb = sb + SM_B + p * 32768;

        // -------- phase A --------
        if (tid < BN) {   // stage sqb/cid for this tile (read early, used in phase B)
            int j = t * BN + tid;
            ((float*)(smem + SM_SQB))[p * 32 + tid] = g_sq[j];
            ((int*)(smem + SM_CIDB))[p * 32 + tid]  = g_cid[j];
        }

        float acc0[4] = {0, 0, 0, 0}, acc1[4] = {0, 0, 0, 0};
        float acc2[4] = {0, 0, 0, 0}, acc3[4] = {0, 0, 0, 0};

#pragma unroll
        for (int ks = 0; ks < 8; ++ks) {
            const int c0 = kh * 16 + ks * 2;
            const uint32_t cA = (uint32_t)((c0 + a_cad) ^ a_sw) << 4;
            const uint32_t cB = (uint32_t)((c0 + b_cad) ^ lr) << 4;

            uint32_t ah0, ah1, ah2, ah3, al0, al1, al2, al3;
            uint32_t bh0, bh1, bh2, bh3, bh4, bh5, bh6, bh7;
            uint32_t bl0, bl1, bl2, bl3, bl4, bl5, bl6, bl7;

            LDSM4(ah0, ah1, ah2, ah3, a_rbase + cA);
            LDSM4(bh0, bh1, bh2, bh3, Bb + boff1 + cB);
            LDSM4(bh4, bh5, bh6, bh7, Bb + boff2 + cB);
            LDSM4(bl0, bl1, bl2, bl3, Bb + 16384 + boff1 + cB);
            LDSM4(bl4, bl5, bl6, bl7, Bb + 16384 + boff2 + cB);
            LDSM4(al0, al1, al2, al3, a_rbase + 32768 + cA);

            MMA16816(acc0, ah0, ah1, ah2, ah3, bh0, bh1);   // hi*hi
            MMA16816(acc1, ah0, ah1, ah2, ah3, bh2, bh3);
            MMA16816(acc2, ah0, ah1, ah2, ah3, bh4, bh5);
            MMA16816(acc3, ah0, ah1, ah2, ah3, bh6, bh7);
            MMA16816(acc0, ah0, ah1, ah2, ah3, bl0, bl1);   // hi*lo
            MMA16816(acc1, ah0, ah1, ah2, ah3, bl2, bl3);
            MMA16816(acc2, ah0, ah1, ah2, ah3, bl4, bl5);
            MMA16816(acc3, ah0, ah1, ah2, ah3, bl6, bl7);
            MMA16816(acc0, al0, al1, al2, al3, bh0, bh1);   // lo*hi
            MMA16816(acc1, al0, al1, al2, al3, bh2, bh3);
            MMA16816(acc2, al0, al1, al2, al3, bh4, bh5);
            MMA16816(acc3, al0, al1, al2, al3, bh6, bh7);
        }

        // store D half
        {
            float* Dk = (float*)(smem + SM_D + kh * 8704);
            int dr = warpM * 16 + (lane >> 2);
            int dc = (lane & 3) * 2;
            *(float2*)&Dk[dr * 34 + 0 + dc]        = make_float2(acc0[0], acc0[1]);
            *(float2*)&Dk[(dr + 8) * 34 + 0 + dc]  = make_float2(acc0[2], acc0[3]);
            *(float2*)&Dk[dr * 34 + 8 + dc]        = make_float2(acc1[0], acc1[1]);
            *(float2*)&Dk[(dr + 8) * 34 + 8 + dc]  = make_float2(acc1[2], acc1[3]);
            *(float2*)&Dk[dr * 34 + 16 + dc]       = make_float2(acc2[0], acc2[1]);
            *(float2*)&Dk[(dr + 8) * 34 + 16 + dc] = make_float2(acc2[2], acc2[3]);
            *(float2*)&Dk[dr * 34 + 24 + dc]       = make_float2(acc3[0], acc3[1]);
            *(float2*)&Dk[(dr + 8) * 34 + 24 + dc] = make_float2(acc3[2], acc3[3]);
        }
        __syncthreads();

        // -------- phase B --------
        // prefetch tile t+2 into buf p (fully consumed by this tile's MMA)
        if (t + 2 < NT) {
            const uint32_t* src = g_Bblk + (size_t)(t + 2) * 8192;
            const uint32_t dst = sb + SM_B + p * 32768;
#pragma unroll
            for (int i = 0; i < 8; ++i) {
                int ck = tid + i * 256;
                cp16(dst + ck * 16, src + ck * 4);
            }
            cp_commit();
        }

        // selection: 2 threads per row, 16 cols each
        if (tid < 128) {
            const float* D0 = (const float*)(smem + SM_D);
            const float* D1 = (const float*)(smem + SM_D + 8704);
            const float* sqb  = (const float*)(smem + SM_SQB) + p * 32;
            const int*   cidb = (const int*)(smem + SM_CIDB) + p * 32;
            const int base = selrow * 34 + selh * 16;
            const int cb   = selh * 16;
#pragma unroll 4
            for (int c = 0; c < 16; ++c) {
                float dot = D0[base + c] + D1[base + c];
                float d2 = fmaxf(sqa_r + sqb[cb + c] - 2.f * dot, 0.f);
                if (d2 < thr) {
                    int cj = cidb[cb + c];
                    if (cnt < KEEP) {
                        int q = cnt++;
                        while (q > 0 && rv[q - 1] > d2) { rv[q] = rv[q - 1]; rc[q] = rc[q - 1]; --q; }
                        rv[q] = d2; rc[q] = cj;
                        if (cnt == KEEP) thr = rv[KEEP - 1];
                    } else {
                        int q = KEEP - 1;
                        while (q > 0 && rv[q - 1] > d2) { rv[q] = rv[q - 1]; rc[q] = rc[q - 1]; --q; }
                        rv[q] = d2; rc[q] = cj;
                        thr = rv[KEEP - 1];
                    }
                }
            }
        }

        if (t + 2 < NT) cp_wait<1>(); else cp_wait<0>();
        __syncthreads();
    }

    // ---- final: merge the two half-lists per row, entropy, output ----
    if (tid < BM) {
        const float* av = (const float*)(smem + SM_SLV) + (2 * tid) * KEEP;
        const int*   ac = (const int*)(smem + SM_SLC) + (2 * tid) * KEEP;
        const float* bv = av + KEEP;
        const int*   bc = ac + KEEP;

        float mv[KEEP]; int mc[KEEP];
        int ia = 0, ib = 0;
#pragma unroll
        for (int i = 0; i < KEEP; ++i) {
            float va = av[ia], vb = bv[ib];
            if (va <= vb) { mv[i] = va; mc[i] = ac[ia]; ++ia; }
            else          { mv[i] = vb; mc[i] = bc[ib]; ++ib; }
        }

        float thrv = mv[KEEP - 1];
        int n = 0;
        while (n < KSEL && mv[n] < thrv) ++n;
        float fn = (float)n, ent = 0.f;
        for (int pp = 0; pp < n; ++pp) {
            bool first = true;
            for (int q = 0; q < pp; ++q)
                if (mc[q] == mc[pp]) { first = false; break; }
            if (!first) continue;
            int cc = 1;
            for (int q = pp + 1; q < n; ++q) cc += (mc[q] == mc[pp]);
            float bins = (float)cc / fn;
            ent -= bins * logf(bins + 1e-5f);
        }
        out[row0 + tid] = ent * g_maxp[row0 + tid];
    }
}

// ---------------------------------------------------------------------------
extern "C" void kernel_launch(void* const* d_in, const int* in_sizes, int n_in,
                              void* d_out, int out_size) {
    const float* enc = (const float*)d_in[0];
    const float* cat = (const float*)d_in[1];
    float* out = (float*)d_out;

    cudaFuncSetAttribute(hmma_main,
                         cudaFuncAttributeMaxDynamicSharedMemorySize, SMEM_BYTES);

    prep_kernel<<<NB * 32 / NTHR, NTHR>>>(enc, cat);
    prep_b_kernel<<<NB * 32 / NTHR, NTHR>>>(enc);
    hmma_main<<<NB / BM, NTHR, SMEM_BYTES>>>(out);
}

// round 4
// speedup vs baseline: 2.4754x; 1.9151x over previous
#include <cuda_runtime.h>
#include <cuda_bf16.h>
#include <math.h>
#include <float.h>
#include <stdint.h>

#define NB    8192
#define ENCD  256
#define NCL   32
#define KSEL  25
#define KEEP  26
#define BM    64          // rows per CTA
#define BN    64          // cols per tile
#define NT    (NB / BN)   // 128 tiles
#define NCHUNK (NT * 2)   // 256 k128-chunks
#define NTHR  256

// ---------------- device scratch ----------------
__device__ float    g_sq[NB];
__device__ float    g_maxp[NB];
__device__ int      g_cid[NB];
// Pre-swizzled bf16 blobs: per 32-row block jb, 32KB = [hi 16KB | lo 16KB],
// row stride 512B, per-row 16B-chunk XOR swizzle (c ^ (r&7)).
__device__ uint32_t g_Bblk[NB * 256];   // 8 MB

// ---------------- helpers ----------------
__device__ __forceinline__ uint32_t smem_to_u32(const void* p) {
    uint32_t a;
    asm("{ .reg .u64 t; cvta.to.shared.u64 t, %1; cvt.u32.u64 %0, t; }" : "=r"(a) : "l"(p));
    return a;
}
__device__ __forceinline__ void cp16(uint32_t s, const void* g) {
    asm volatile("cp.async.cg.shared.global [%0], [%1], 16;" :: "r"(s), "l"(g) : "memory");
}
__device__ __forceinline__ void cp_commit() {
    asm volatile("cp.async.commit_group;" ::: "memory");
}
template <int N>
__device__ __forceinline__ void cp_wait() {
    asm volatile("cp.async.wait_group %0;" :: "n"(N) : "memory");
}
#define LDSM4(r0, r1, r2, r3, addr) \
    asm volatile("ldmatrix.sync.aligned.m8n8.x4.shared.b16 {%0,%1,%2,%3}, [%4];" \
                 : "=r"(r0), "=r"(r1), "=r"(r2), "=r"(r3) : "r"(addr))
#define MMA16816(d, a0, a1, a2, a3, b0, b1) \
    asm volatile("mma.sync.aligned.m16n8k16.row.col.f32.bf16.bf16.f32 " \
                 "{%0,%1,%2,%3}, {%4,%5,%6,%7}, {%8,%9}, {%0,%1,%2,%3};" \
                 : "+f"((d)[0]), "+f"((d)[1]), "+f"((d)[2]), "+f"((d)[3]) \
                 : "r"(a0), "r"(a1), "r"(a2), "r"(a3), "r"(b0), "r"(b1))

// ---------------- smem layout (bytes) ----------------
#define SM_A     0        // 64KB: A hi [64][512B], then A lo at +32768
#define SM_B     65536    // 2 x 32KB chunk bufs ([hi 16KB | lo 16KB], row stride 256B)
#define SM_CAND  131072   // 64 rows x 64 cap x 4B packed candidates
#define SM_RV    147456   // 64 x 26 f32 packed top-lists
#define SM_SQA   154112   // 64 f32
#define SM_SQB   154368   // 64 f32
#define SM_CIDB  154624   // 64 int
#define SM_THR   154880   // 64 f32 (packed)
#define SM_CN    155136   // 64 int
#define SMEM_BYTES 155392

// ---------------------------------------------------------------------------
// prep1: row sum-of-squares; argmax/max of categorical. One warp per row.
// ---------------------------------------------------------------------------
__global__ void prep_kernel(const float* __restrict__ enc,
                            const float* __restrict__ cat) {
    int warp = (blockIdx.x * blockDim.x + threadIdx.x) >> 5;
    int lane = threadIdx.x & 31;
    if (warp >= NB) return;

    const float* e = enc + (size_t)warp * ENCD;
    float s = 0.f;
#pragma unroll
    for (int i = 0; i < ENCD / 32; ++i) { float v = e[lane + 32 * i]; s += v * v; }
#pragma unroll
    for (int off = 16; off; off >>= 1) s += __shfl_xor_sync(0xffffffffu, s, off);

    float v = cat[(size_t)warp * NCL + lane];
    int idx = lane;
#pragma unroll
    for (int off = 16; off; off >>= 1) {
        float ov = __shfl_xor_sync(0xffffffffu, v, off);
        int   oi = __shfl_xor_sync(0xffffffffu, idx, off);
        if (ov > v || (ov == v && oi < idx)) { v = ov; idx = oi; }
    }
    if (lane == 0) { g_sq[warp] = s; g_maxp[warp] = v; g_cid[warp] = idx; }
}

// ---------------------------------------------------------------------------
// prep2: bf16 hi/lo split into pre-swizzled 32-row blobs.
// ---------------------------------------------------------------------------
__global__ void prep_b_kernel(const float* __restrict__ E) {
    int gid = blockIdx.x * blockDim.x + threadIdx.x;   // NB*32 threads
    int jb = gid >> 10;
    int r  = (gid >> 5) & 31;
    int c  = gid & 31;

    const float* src = E + (size_t)(jb * 32 + r) * ENCD + c * 8;
    float4 v0 = *(const float4*)src;
    float4 v1 = *(const float4*)(src + 4);
    float f[8] = {v0.x, v0.y, v0.z, v0.w, v1.x, v1.y, v1.z, v1.w};

    uint32_t hi[4], lo[4];
#pragma unroll
    for (int i = 0; i < 4; ++i) {
        __nv_bfloat16 h0 = __float2bfloat16(f[2 * i]);
        __nv_bfloat16 h1 = __float2bfloat16(f[2 * i + 1]);
        __nv_bfloat16 l0 = __float2bfloat16(f[2 * i] - __bfloat162float(h0));
        __nv_bfloat16 l1 = __float2bfloat16(f[2 * i + 1] - __bfloat162float(h1));
        __nv_bfloat162 hp; hp.x = h0; hp.y = h1;
        __nv_bfloat162 lp; lp.x = l0; lp.y = l1;
        hi[i] = *(uint32_t*)&hp;
        lo[i] = *(uint32_t*)&lp;
    }

    int base = jb * 8192;                                   // u32 units (32KB blob)
    int off  = (r * 512 + ((c ^ (r & 7)) << 4)) >> 2;       // u32 units
    *(uint4*)(g_Bblk + base + off)        = make_uint4(hi[0], hi[1], hi[2], hi[3]);
    *(uint4*)(g_Bblk + base + 4096 + off) = make_uint4(lo[0], lo[1], lo[2], lo[3]);
}

// ---------------------------------------------------------------------------
// Main: 128 CTAs x 64 rows; sweep 128 column tiles of 64 (as 256 k128-chunks).
// 8 warps = 2m x 4n; warp tile m32 x n16, full K, D in registers.
// Fused in-register selection with rare candidate pushes.
// ---------------------------------------------------------------------------
__global__ void __launch_bounds__(NTHR, 1)
hmma_main(float* __restrict__ out) {
    extern __shared__ char smem[];
    const uint32_t sb = smem_to_u32(smem);
    const int tid  = threadIdx.x;
    const int lane = tid & 31;
    const int wid  = tid >> 5;
    const int mw   = wid & 1;        // 0/1 -> rows mw*32..+32
    const int nw   = wid >> 1;       // 0..3 -> cols nw*16..+16
    const int row0 = blockIdx.x * BM;
    const int b2   = blockIdx.x * 2; // A blob pair

    float* s_sqa  = (float*)(smem + SM_SQA);
    float* s_sqb  = (float*)(smem + SM_SQB);
    int*   s_cidb = (int*)(smem + SM_CIDB);
    float* s_thr  = (float*)(smem + SM_THR);
    int*   s_cn   = (int*)(smem + SM_CN);
    uint32_t* s_cand = (uint32_t*)(smem + SM_CAND);
    float* s_rv   = (float*)(smem + SM_RV);

    // ---- prologue: A (64KB) + chunk0 as group0; chunk1 as group1 ----
#pragma unroll
    for (int i = 0; i < 16; ++i) {
        int ck = tid + i * 256;                 // 0..4095 16B pieces
        int p  = ck >> 10;                      // (blob, hilo): p>>1 = blob, p&1 = hilo
        int off = ck & 1023;
        const uint32_t* src = g_Bblk + (size_t)(b2 + (p >> 1)) * 8192
                                     + (size_t)(p & 1) * 4096 + off * 4;
        cp16(sb + SM_A + (uint32_t)(p & 1) * 32768u + (uint32_t)(p >> 1) * 16384u + off * 16, src);
    }
    // chunk 0 (t=0, h=0) into buf 0
#pragma unroll
    for (int i = 0; i < 8; ++i) {
        int ci = tid + i * 256;
        int hilo = ci >> 10, j = (ci >> 4) & 63, c = ci & 15;
        const uint32_t* src = g_Bblk + (size_t)(j >> 5) * 8192 + (size_t)hilo * 4096
                                     + (j & 31) * 128 + c * 4;
        cp16(sb + SM_B + hilo * 16384u + j * 256u + c * 16u, src);
    }
    cp_commit();   // group: A + chunk0
    // chunk 1 (t=0, h=1) into buf 1
#pragma unroll
    for (int i = 0; i < 8; ++i) {
        int ci = tid + i * 256;
        int hilo = ci >> 10, j = (ci >> 4) & 63, c = ci & 15;
        const uint32_t* src = g_Bblk + (size_t)(j >> 5) * 8192 + (size_t)hilo * 4096
                                     + (j & 31) * 128 + 64 + c * 4;
        cp16(sb + SM_B + 32768u + hilo * 16384u + j * 256u + c * 16u, src);
    }
    cp_commit();   // group: chunk1

    if (tid < BM) {
        s_sqa[tid] = g_sq[row0 + tid];
        s_thr[tid] = FLT_MAX;
        s_cn[tid]  = 0;
    }

    // ---- per-lane ldmatrix addressing ----
    const int lr = lane & 7, gq = lane >> 3;
    // A rows for msub 0/1: order (r0-7,c0)(r8-15,c0)(r0-7,c1)(r8-15,c1)
    int a_row0 = mw * 32 + ((gq & 1) << 3) + lr;
    int a_row1 = a_row0 + 16;
    const uint32_t a_base0 = sb + SM_A + a_row0 * 512;
    const uint32_t a_base1 = sb + SM_A + a_row1 * 512;
    const int a_sw0 = a_row0 & 7, a_sw1 = a_row1 & 7;
    const int a_cb  = gq >> 1;     // chunk bit within kstep
    // B rows: order (n0-7,c0)(n0-7,c1)(n8-15,c0)(n8-15,c1)
    const int j_l  = nw * 16 + ((gq >> 1) << 3) + lr;
    const int b_sw = j_l & 7;
    const int b_cb = gq & 1;
    const uint32_t b_roff = j_l * 256;

    // selection state (maintainer = tid<64 owns row tid)
    int mcnt = 0;

    // accumulators: [msub][nsub][4]
    float acc[2][2][4];

    // epilogue row/col constants
    const int q = lane >> 2;
    const int e0 = (lane & 3) * 2;

#pragma unroll 1
    for (int gc = 0; gc < NCHUNK; ++gc) {
        const int t = gc >> 1, h = gc & 1;
        const uint32_t Bb = sb + SM_B + (uint32_t)(gc & 1) * 32768u;

        cp_wait<1>();
        __syncthreads();   // chunk gc visible to all

        if (h == 0) {
#pragma unroll
            for (int ms = 0; ms < 2; ++ms)
#pragma unroll
                for (int ns = 0; ns < 2; ++ns)
#pragma unroll
                    for (int c = 0; c < 4; ++c) acc[ms][ns][c] = 0.f;
        } else if (tid < BN) {
            int j = t * BN + tid;
            s_sqb[tid]  = g_sq[j];
            s_cidb[tid] = g_cid[j];
        }

        // ---- compute chunk: 8 ksteps x (6 LDSM4 + 12 MMA) ----
        const uint32_t aho = (uint32_t)h * 256u;            // A k-half byte offset
#pragma unroll
        for (int s = 0; s < 8; ++s) {
            const int kc = s * 2;
            uint32_t ah0[4], ah1[4], al0[4], al1[4], bh[4], bl[4];
            LDSM4(ah0[0], ah0[1], ah0[2], ah0[3], a_base0 + aho + (uint32_t)(((kc + a_cb) ^ a_sw0) << 4));
            LDSM4(ah1[0], ah1[1], ah1[2], ah1[3], a_base1 + aho + (uint32_t)(((kc + a_cb) ^ a_sw1) << 4));
            LDSM4(bh[0], bh[1], bh[2], bh[3], Bb + b_roff + (uint32_t)(((kc + b_cb) ^ b_sw) << 4));
            LDSM4(bl[0], bl[1], bl[2], bl[3], Bb + 16384u + b_roff + (uint32_t)(((kc + b_cb) ^ b_sw) << 4));
            LDSM4(al0[0], al0[1], al0[2], al0[3], a_base0 + 32768u + aho + (uint32_t)(((kc + a_cb) ^ a_sw0) << 4));
            LDSM4(al1[0], al1[1], al1[2], al1[3], a_base1 + 32768u + aho + (uint32_t)(((kc + a_cb) ^ a_sw1) << 4));

            MMA16816(acc[0][0], ah0[0], ah0[1], ah0[2], ah0[3], bh[0], bh[1]);  // hi*hi
            MMA16816(acc[0][1], ah0[0], ah0[1], ah0[2], ah0[3], bh[2], bh[3]);
            MMA16816(acc[1][0], ah1[0], ah1[1], ah1[2], ah1[3], bh[0], bh[1]);
            MMA16816(acc[1][1], ah1[0], ah1[1], ah1[2], ah1[3], bh[2], bh[3]);
            MMA16816(acc[0][0], ah0[0], ah0[1], ah0[2], ah0[3], bl[0], bl[1]);  // hi*lo
            MMA16816(acc[0][1], ah0[0], ah0[1], ah0[2], ah0[3], bl[2], bl[3]);
            MMA16816(acc[1][0], ah1[0], ah1[1], ah1[2], ah1[3], bl[0], bl[1]);
            MMA16816(acc[1][1], ah1[0], ah1[1], ah1[2], ah1[3], bl[2], bl[3]);
            MMA16816(acc[0][0], al0[0], al0[1], al0[2], al0[3], bh[0], bh[1]);  // lo*hi
            MMA16816(acc[0][1], al0[0], al0[1], al0[2], al0[3], bh[2], bh[3]);
            MMA16816(acc[1][0], al1[0], al1[1], al1[2], al1[3], bh[0], bh[1]);
            MMA16816(acc[1][1], al1[0], al1[1], al1[2], al1[3], bh[2], bh[3]);
        }

        __syncthreads();   // all LDSM of this buf done -> safe to overwrite

        // prefetch chunk gc+2 into this buf
        if (gc + 2 < NCHUNK) {
            const int t2 = (gc + 2) >> 1, h2 = (gc + 2) & 1;
#pragma unroll
            for (int i = 0; i < 8; ++i) {
                int ci = tid + i * 256;
                int hilo = ci >> 10, j = (ci >> 4) & 63, c = ci & 15;
                const uint32_t* src = g_Bblk + (size_t)(2 * t2 + (j >> 5)) * 8192
                                             + (size_t)hilo * 4096 + (j & 31) * 128
                                             + h2 * 64 + c * 4;
                cp16(Bb + hilo * 16384u + j * 256u + c * 16u, src);
            }
        }
        cp_commit();

        if (h == 1) {
            // ---- fused epilogue: d2 + threshold check + rare push ----
#pragma unroll
            for (int ms = 0; ms < 2; ++ms) {
#pragma unroll
                for (int ro = 0; ro < 2; ++ro) {
                    const int row = mw * 32 + ms * 16 + ro * 8 + q;
                    const float sqa = s_sqa[row];
                    const float thr = s_thr[row];
#pragma unroll
                    for (int ns = 0; ns < 2; ++ns) {
#pragma unroll
                        for (int e = 0; e < 2; ++e) {
                            const int col = nw * 16 + ns * 8 + e0 + e;
                            float dot = acc[ms][ns][ro * 2 + e];
                            float d2 = fmaxf(sqa + s_sqb[col] - 2.f * dot, 0.f);
                            uint32_t pk = (__float_as_uint(d2) & 0xFFFFFFE0u)
                                          | (uint32_t)s_cidb[col];
                            if (__uint_as_float(pk) < thr) {
                                int pos = atomicAdd(&s_cn[row], 1);
                                s_cand[row * 64 + pos] = pk;
                            }
                        }
                    }
                }
            }
            __syncthreads();

            // ---- maintainers: merge candidates into sorted top-26 ----
            if (tid < BM) {
                int n = s_cn[tid];
                float* rv = s_rv + tid * KEEP;
                for (int i = 0; i < n; ++i) {
                    float v = __uint_as_float(s_cand[tid * 64 + i]);
                    if (mcnt < KEEP) {
                        int p = mcnt++;
                        while (p > 0 && rv[p - 1] > v) { rv[p] = rv[p - 1]; --p; }
                        rv[p] = v;
                    } else if (v < rv[KEEP - 1]) {
                        int p = KEEP - 1;
                        while (p > 0 && rv[p - 1] > v) { rv[p] = rv[p - 1]; --p; }
                        rv[p] = v;
                    }
                }
                s_thr[tid] = (mcnt == KEEP) ? rv[KEEP - 1] : FLT_MAX;
                s_cn[tid] = 0;
            }
            __syncthreads();
        }
    }

    // ---- final: entropy per row ----
    if (tid < BM) {
        const float* rv = s_rv + tid * KEEP;
        float t25 = rv[KEEP - 1];
        int n = 0;
        while (n < KSEL && rv[n] < t25) ++n;
        int cid[KSEL];
        for (int p = 0; p < n; ++p) cid[p] = (int)(__float_as_uint(rv[p]) & 31u);
        float fn = (float)n, ent = 0.f;
        for (int p = 0; p < n; ++p) {
            bool first = true;
            for (int qq = 0; qq < p; ++qq)
                if (cid[qq] == cid[p]) { first = false; break; }
            if (!first) continue;
            int cc = 1;
            for (int qq = p + 1; qq < n; ++qq) cc += (cid[qq] == cid[p]);
            float bins = (float)cc / fn;
            ent -= bins * logf(bins + 1e-5f);
        }
        out[row0 + tid] = ent * g_maxp[row0 + tid];
    }
}

// ---------------------------------------------------------------------------
extern "C" void kernel_launch(void* const* d_in, const int* in_sizes, int n_in,
                              void* d_out, int out_size) {
    const float* enc = (const float*)d_in[0];
    const float* cat = (const float*)d_in[1];
    float* out = (float*)d_out;

    cudaFuncSetAttribute(hmma_main,
                         cudaFuncAttributeMaxDynamicSharedMemorySize, SMEM_BYTES);

    prep_kernel<<<NB * 32 / NTHR, NTHR>>>(enc, cat);
    prep_b_kernel<<<NB * 32 / NTHR, NTHR>>>(enc);
    hmma_main<<<NB / BM, NTHR, SMEM_BYTES>>>(out);
}